// round 11
// baseline (speedup 1.0000x reference)
#include <cuda_runtime.h>
#include <cuda_fp16.h>
#include <cuda_bf16.h>
#include <mma.h>
#include <math.h>

using namespace nvcuda;

// Problem constants (fixed by the dataset)
#define NNODES 100000
#define MAXE   1600000
#define NFEAT  128
#define NHID   64
#define NCLASS 16

#define NB   592          // 4 blocks/SM x 148 SMs -- co-resident guaranteed
#define NTH  256

// Scratch buffers.
__device__ __align__(128) uint4  g_sup1h[NNODES * 8];   // N x 64 fp16 (x @ W1)
__device__ __align__(128) __half g_sup2h[NNODES * 16];  // N x 16 fp16 (h @ W2)
__device__ int  g_cnt[NNODES];       // degree counts, then permute cursor
__device__ int  g_off[NNODES + 1];   // CSR offsets
__device__ int2 g_csr[MAXE];         // packed {src, float_as_int(w)}
__device__ int  g_ctrl[128];         // [0] gathers barrier, [8..105] scan aggs; memset per call

// Device-wide barrier for the persistent gathers kernel.
__device__ __forceinline__ void gbar(int* ctrl, int i, int nb) {
    __syncthreads();
    if (threadIdx.x == 0) {
        __threadfence();
        atomicAdd(&ctrl[i], 1);
        while (((volatile int*)ctrl)[i] < nb) __nanosleep(64);
    }
    __syncthreads();
}

// ---------------------------------------------------------------------------
// GEMM1 (HMMA): sup1[N,64] = x[N,128] @ W1[128,64], fp16 in, fp32 acc,
// fp16 out. 128x64 block tile, KC=64 (2 phases), 8 warps, warp = 16 rows.
// ---------------------------------------------------------------------------
__global__ void __launch_bounds__(256) gemm1_kernel(
        const float* __restrict__ x,
        const float* __restrict__ W1,
        uint4* __restrict__ outh, int N) {
    __shared__ __align__(16) char smem[32768];
    __half (*sA)[72] = (__half(*)[72])smem;                  // 128 x 72 halves
    __half (*sB)[72] = (__half(*)[72])(smem + 128 * 72 * 2); // 64 x 72 halves
    float (*sO)[64]  = (float(*)[64])smem;                   // epilogue alias

    int tid = threadIdx.x;
    int w = tid >> 5;
    int lane = tid & 31;
    int rb = blockIdx.x * 128;

    wmma::fragment<wmma::accumulator, 16, 16, 16, float> acc[4];
#pragma unroll
    for (int i = 0; i < 4; i++) wmma::fill_fragment(acc[i], 0.f);

#pragma unroll
    for (int kb = 0; kb < NFEAT; kb += 64) {
#pragma unroll
        for (int it = 0; it < 8; it++) {
            int idx = tid + it * 256;
            int row = idx >> 4;
            int cc = (idx & 15) * 4;
            float4 v = make_float4(0.f, 0.f, 0.f, 0.f);
            if (rb + row < N)
                v = *(const float4*)&x[(size_t)(rb + row) * NFEAT + kb + cc];
            *(__half2*)&sA[row][cc]     = __floats2half2_rn(v.x, v.y);
            *(__half2*)&sA[row][cc + 2] = __floats2half2_rn(v.z, v.w);
        }
#pragma unroll
        for (int it = 0; it < 4; it++) {
            int idx = tid + it * 256;
            int row = idx >> 4;
            int cc = (idx & 15) * 4;
            float4 v = *(const float4*)&W1[(size_t)(kb + row) * NHID + cc];
            *(__half2*)&sB[row][cc]     = __floats2half2_rn(v.x, v.y);
            *(__half2*)&sB[row][cc + 2] = __floats2half2_rn(v.z, v.w);
        }
        __syncthreads();

#pragma unroll
        for (int ks = 0; ks < 64; ks += 16) {
            wmma::fragment<wmma::matrix_a, 16, 16, 16, __half, wmma::row_major> fa;
            wmma::load_matrix_sync(fa, &sA[w * 16][ks], 72);
#pragma unroll
            for (int nt = 0; nt < 4; nt++) {
                wmma::fragment<wmma::matrix_b, 16, 16, 16, __half, wmma::row_major> fb;
                wmma::load_matrix_sync(fb, &sB[ks][nt * 16], 72);
                wmma::mma_sync(acc[nt], fa, fb, acc[nt]);
            }
        }
        __syncthreads();
    }

#pragma unroll
    for (int nt = 0; nt < 4; nt++)
        wmma::store_matrix_sync(&sO[w * 16][nt * 16], acc[nt], 64, wmma::mem_row_major);
    __syncwarp();

#pragma unroll
    for (int q = 0; q < 4; q++) {
        int idx = lane + q * 32;
        int r = idx >> 3;
        int c8 = idx & 7;
        int row = rb + w * 16 + r;
        if (row < N) {
            const float* p = &sO[w * 16 + r][c8 * 8];
            __half2 h0 = __floats2half2_rn(p[0], p[1]);
            __half2 h1 = __floats2half2_rn(p[2], p[3]);
            __half2 h2 = __floats2half2_rn(p[4], p[5]);
            __half2 h3 = __floats2half2_rn(p[6], p[7]);
            uint4 o;
            o.x = *(unsigned*)&h0; o.y = *(unsigned*)&h1;
            o.z = *(unsigned*)&h2; o.w = *(unsigned*)&h3;
            outh[(size_t)row * 8 + c8] = o;
        }
    }
}

// ---------------------------------------------------------------------------
// CSR build (split kernels -- R7 proven-best form)
// ---------------------------------------------------------------------------
__global__ void hist_kernel(const int* __restrict__ dst, int* __restrict__ cnt, int E) {
    int e = blockIdx.x * blockDim.x + threadIdx.x;
    if (e < E) atomicAdd(&cnt[dst[e]], 1);
}

// Fused exclusive scan with decoupled lookback (98 blocks). Also initializes
// the permute cursor. Deadlock-free: blocks only wait on lower block ids.
__global__ void __launch_bounds__(1024) scan_fused(
        const int* __restrict__ cnt,
        int* __restrict__ off,
        int* __restrict__ cursor,
        volatile int* __restrict__ aggp,   // zeroed before launch; agg+1
        int n, int E) {
    __shared__ int s[1024];
    __shared__ int s_prefix;
    int b = blockIdx.x;
    int i = b * 1024 + threadIdx.x;
    int v = (i < n) ? cnt[i] : 0;
    s[threadIdx.x] = v;
    __syncthreads();
#pragma unroll
    for (int d = 1; d < 1024; d <<= 1) {
        int t = (threadIdx.x >= d) ? s[threadIdx.x - d] : 0;
        __syncthreads();
        s[threadIdx.x] += t;
        __syncthreads();
    }
    int local_excl = s[threadIdx.x] - v;
    int total = s[1023];

    if (threadIdx.x == 0) {
        __threadfence();
        aggp[b] = total + 1;
    }

    int contrib = 0;
    if (threadIdx.x < (unsigned)b) {
        int a;
        do { a = aggp[threadIdx.x]; } while (a == 0);
        contrib = a - 1;
    }
    __syncthreads();
    s[threadIdx.x] = contrib;
    __syncthreads();
#pragma unroll
    for (int d = 512; d; d >>= 1) {
        if (threadIdx.x < d) s[threadIdx.x] += s[threadIdx.x + d];
        __syncthreads();
    }
    if (threadIdx.x == 0) s_prefix = s[0];
    __syncthreads();
    int prefix = s_prefix;

    if (i < n) {
        int o = local_excl + prefix;
        off[i] = o;
        cursor[i] = o;
    }
    if (i == 0) off[n] = E;
}

// Two independent edge chains per thread (e and e+half), both coalesced.
__global__ void __launch_bounds__(256) permute_kernel(
        const int* __restrict__ src,
        const int* __restrict__ dst,
        const float* __restrict__ ew,
        int* __restrict__ cursor,
        int2* __restrict__ csr, int E, int half) {
    int g = blockIdx.x * blockDim.x + threadIdx.x;
    int e0 = g;
    int e1 = g + half;
    bool v0 = e0 < half;
    bool v1 = e1 < E;
    int d0 = v0 ? dst[e0] : 0;
    int d1 = v1 ? dst[e1] : 0;
    int s0 = v0 ? src[e0] : 0;
    int s1 = v1 ? src[e1] : 0;
    float w0 = v0 ? ew[e0] : 0.f;
    float w1 = v1 ? ew[e1] : 0.f;
    int p0 = v0 ? atomicAdd(&cursor[d0], 1) : 0;
    int p1 = v1 ? atomicAdd(&cursor[d1], 1) : 0;
    if (v0) csr[p0] = make_int2(s0, __float_as_int(w0));
    if (v1) csr[p1] = make_int2(s1, __float_as_int(w1));
}

// ---------------------------------------------------------------------------
// Fused gathers (persistent, NB blocks co-resident, warp-strided over nodes):
//   Phase A: agg1 = adj @ sup1 (fp16 gather, MLP-8), h = relu(+b1),
//            sup2 = fp16(h @ W2) via per-warp smem row.
//   gbar
//   Phase B: agg2 = adj @ sup2 (fp16), +b2, 16-wide log_softmax.
// W2/b1 loaded to smem ONCE per block (592 blocks) instead of 12,500.
// ---------------------------------------------------------------------------
__global__ void __launch_bounds__(256, 4) gathers_kernel(
        const int* __restrict__ off,
        const int2* __restrict__ csr,
        const unsigned* __restrict__ suph,   // N x 32 half2 words
        const float* __restrict__ b1,
        const float* __restrict__ W2,
        const float* __restrict__ b2,
        __half* __restrict__ sup2h,
        float* __restrict__ out,
        int* __restrict__ ctrl, int N) {
    __shared__ float sW[NHID * NCLASS];  // 4 KB
    __shared__ float sb[NHID];
    __shared__ float sh[8][NHID];        // per-warp h row
    for (int i = threadIdx.x; i < NHID * NCLASS; i += blockDim.x) sW[i] = W2[i];
    if (threadIdx.x < NHID) sb[threadIdx.x] = b1[threadIdx.x];
    __syncthreads();

    int wid = threadIdx.x >> 5;
    int lane = threadIdx.x & 31;
    int gw = blockIdx.x * 8 + wid;
    int TW = gridDim.x * 8;

    // ---- Phase A: layer-1 aggregation + relu + W2 projection ----
    for (int node = gw; node < N; node += TW) {
        int beg = off[node], end = off[node + 1];
        float ax = 0.f, ay = 0.f;
        int j = beg;
        for (; j + 8 <= end; j += 8) {
            int2 e[8];
            unsigned u[8];
#pragma unroll
            for (int q = 0; q < 8; q++) e[q] = csr[j + q];
#pragma unroll
            for (int q = 0; q < 8; q++) u[q] = suph[(size_t)e[q].x * 32 + lane];
#pragma unroll
            for (int q = 0; q < 8; q++) {
                float w = __int_as_float(e[q].y);
                float2 f = __half22float2(*(__half2*)&u[q]);
                ax += w * f.x;
                ay += w * f.y;
            }
        }
        for (; j + 2 <= end; j += 2) {
            int2 e0 = csr[j], e1 = csr[j + 1];
            unsigned u0 = suph[(size_t)e0.x * 32 + lane];
            unsigned u1 = suph[(size_t)e1.x * 32 + lane];
            float w0 = __int_as_float(e0.y), w1 = __int_as_float(e1.y);
            float2 f0 = __half22float2(*(__half2*)&u0);
            float2 f1 = __half22float2(*(__half2*)&u1);
            ax += w0 * f0.x + w1 * f1.x;
            ay += w0 * f0.y + w1 * f1.y;
        }
        if (j < end) {
            int2 ed = csr[j];
            float w = __int_as_float(ed.y);
            unsigned u = suph[(size_t)ed.x * 32 + lane];
            float2 f = __half22float2(*(__half2*)&u);
            ax += w * f.x;
            ay += w * f.y;
        }
        sh[wid][2 * lane]     = fmaxf(ax + sb[2 * lane], 0.f);
        sh[wid][2 * lane + 1] = fmaxf(ay + sb[2 * lane + 1], 0.f);
        __syncwarp();

        int c = lane & 15;
        int kh = lane >> 4;
        float acc = 0.f;
#pragma unroll
        for (int i = 0; i < 32; i++) {
            int k = 2 * i + kh;
            acc += sh[wid][k] * sW[k * NCLASS + c];
        }
        acc += __shfl_down_sync(0xffffffffu, acc, 16);
        if (lane < 16) sup2h[(size_t)node * NCLASS + lane] = __float2half_rn(acc);
        __syncwarp();
    }

    gbar(ctrl, 0, gridDim.x);   // sup2h fully written + visible

    // ---- Phase B: layer-2 aggregation + bias + log_softmax ----
    int l16 = lane & 15;
    int half = lane >> 4;
    float bias = b2[l16];
    for (int node = gw; node < N; node += TW) {
        int beg = off[node], end = off[node + 1];
        float acc = 0.f;
        int j = beg + half;
        for (; j + 6 < end; j += 8) {     // 4 edges per half-warp in flight
            int2 ea = csr[j];
            int2 eb = csr[j + 2];
            int2 ec = csr[j + 4];
            int2 ed = csr[j + 6];
            float va = __half2float(sup2h[(size_t)ea.x * NCLASS + l16]);
            float vb = __half2float(sup2h[(size_t)eb.x * NCLASS + l16]);
            float vc = __half2float(sup2h[(size_t)ec.x * NCLASS + l16]);
            float vd = __half2float(sup2h[(size_t)ed.x * NCLASS + l16]);
            acc += __int_as_float(ea.y) * va + __int_as_float(eb.y) * vb;
            acc += __int_as_float(ec.y) * vc + __int_as_float(ed.y) * vd;
        }
        for (; j < end; j += 2) {
            int2 ed = csr[j];
            acc += __int_as_float(ed.y) * __half2float(sup2h[(size_t)ed.x * NCLASS + l16]);
        }
        acc += __shfl_down_sync(0xffffffffu, acc, 16);

        float v = acc + bias;
        float m = v;
#pragma unroll
        for (int d = 8; d; d >>= 1) m = fmaxf(m, __shfl_xor_sync(0xffffffffu, m, d));
        float ex = expf(v - m);
        float ssum = ex;
#pragma unroll
        for (int d = 8; d; d >>= 1) ssum += __shfl_xor_sync(0xffffffffu, ssum, d);
        float r = v - m - logf(ssum);
        if (lane < 16) out[(size_t)node * NCLASS + lane] = r;
        __syncwarp();
    }
}

extern "C" void kernel_launch(void* const* d_in, const int* in_sizes, int n_in,
                              void* d_out, int out_size) {
    const float* x  = (const float*)d_in[0];
    const int*   src = (const int*)d_in[1];
    const int*   dst = (const int*)d_in[2];
    const float* ew  = (const float*)d_in[3];
    const float* W1  = (const float*)d_in[4];
    const float* b1  = (const float*)d_in[5];
    const float* W2  = (const float*)d_in[6];
    const float* b2  = (const float*)d_in[7];
    float* out = (float*)d_out;

    int N = in_sizes[0] / NFEAT;   // 100000
    int E = in_sizes[1];           // 1600000

    void *p_sup1h, *p_sup2h, *p_cnt, *p_off, *p_csr, *p_ctrl;
    cudaGetSymbolAddress(&p_sup1h, g_sup1h);
    cudaGetSymbolAddress(&p_sup2h, g_sup2h);
    cudaGetSymbolAddress(&p_cnt, g_cnt);
    cudaGetSymbolAddress(&p_off, g_off);
    cudaGetSymbolAddress(&p_csr, g_csr);
    cudaGetSymbolAddress(&p_ctrl, g_ctrl);

    int nb_scan = (N + 1023) / 1024;   // 98

    // Fork: gemm1 on a side stream, overlapped with the CSR build.
    cudaStream_t s1;
    cudaStreamCreateWithFlags(&s1, cudaStreamNonBlocking);
    cudaEvent_t e0, e1;
    cudaEventCreateWithFlags(&e0, cudaEventDisableTiming);
    cudaEventCreateWithFlags(&e1, cudaEventDisableTiming);

    cudaEventRecord(e0, 0);
    cudaStreamWaitEvent(s1, e0, 0);
    gemm1_kernel<<<(N + 127) / 128, 256, 0, s1>>>(x, W1, (uint4*)p_sup1h, N);
    cudaEventRecord(e1, s1);

    // --- CSR build (main stream, split kernels) ---
    cudaMemsetAsync(p_cnt, 0, (size_t)N * sizeof(int));
    cudaMemsetAsync(p_ctrl, 0, 128 * sizeof(int));
    hist_kernel<<<(E + 255) / 256, 256>>>(dst, (int*)p_cnt, E);
    scan_fused<<<nb_scan, 1024>>>((const int*)p_cnt, (int*)p_off, (int*)p_cnt,
                                  (volatile int*)(((int*)p_ctrl) + 8), N, E);
    {
        int half = (E + 1) / 2;
        int blocks = (half + 255) / 256;
        permute_kernel<<<blocks, 256>>>(src, dst, ew, (int*)p_cnt,
                                        (int2*)p_csr, E, half);
    }

    // Join: gathers need both CSR and sup1.
    cudaStreamWaitEvent(0, e1, 0);

    // Fused persistent gathers (both layers, one launch).
    gathers_kernel<<<NB, NTH>>>((const int*)p_off, (const int2*)p_csr,
                                (const unsigned*)p_sup1h, b1, W2, b2,
                                (__half*)p_sup2h, out, (int*)p_ctrl, N);
}

// round 13
// speedup vs baseline: 1.0463x; 1.0463x over previous
#include <cuda_runtime.h>
#include <cuda_fp16.h>
#include <cuda_bf16.h>
#include <mma.h>
#include <math.h>

using namespace nvcuda;

// Problem constants (fixed by the dataset)
#define NNODES 100000
#define MAXE   1600000
#define NFEAT  128
#define NHID   64
#define NCLASS 16

// Scratch buffers.
__device__ __align__(128) uint4  g_sup1h[NNODES * 8];   // N x 64 fp16 (x @ W1)
__device__ __align__(128) __half g_sup2h[NNODES * 16];  // N x 16 fp16 (h @ W2)
__device__ int  g_cnt[NNODES];       // degree counts, then permute cursor
__device__ int  g_off[NNODES + 1];   // CSR offsets
__device__ int2 g_csr[MAXE];         // packed {src, float_as_int(w)}
__device__ int  g_agg[128];          // scan lookback aggregates; memset per call

// ---------------------------------------------------------------------------
// GEMM1 (HMMA): sup1[N,64] = x[N,128] @ W1[128,64], fp16 in, fp32 acc,
// fp16 out. 128x64 block tile, KC=64 (2 phases), 8 warps, warp = 16 rows.
// ---------------------------------------------------------------------------
__global__ void __launch_bounds__(256) gemm1_kernel(
        const float* __restrict__ x,
        const float* __restrict__ W1,
        uint4* __restrict__ outh, int N) {
    __shared__ __align__(16) char smem[32768];
    __half (*sA)[72] = (__half(*)[72])smem;                  // 128 x 72 halves
    __half (*sB)[72] = (__half(*)[72])(smem + 128 * 72 * 2); // 64 x 72 halves
    float (*sO)[64]  = (float(*)[64])smem;                   // epilogue alias

    int tid = threadIdx.x;
    int w = tid >> 5;
    int lane = tid & 31;
    int rb = blockIdx.x * 128;

    wmma::fragment<wmma::accumulator, 16, 16, 16, float> acc[4];
#pragma unroll
    for (int i = 0; i < 4; i++) wmma::fill_fragment(acc[i], 0.f);

#pragma unroll
    for (int kb = 0; kb < NFEAT; kb += 64) {
#pragma unroll
        for (int it = 0; it < 8; it++) {
            int idx = tid + it * 256;
            int row = idx >> 4;
            int cc = (idx & 15) * 4;
            float4 v = make_float4(0.f, 0.f, 0.f, 0.f);
            if (rb + row < N)
                v = *(const float4*)&x[(size_t)(rb + row) * NFEAT + kb + cc];
            *(__half2*)&sA[row][cc]     = __floats2half2_rn(v.x, v.y);
            *(__half2*)&sA[row][cc + 2] = __floats2half2_rn(v.z, v.w);
        }
#pragma unroll
        for (int it = 0; it < 4; it++) {
            int idx = tid + it * 256;
            int row = idx >> 4;
            int cc = (idx & 15) * 4;
            float4 v = *(const float4*)&W1[(size_t)(kb + row) * NHID + cc];
            *(__half2*)&sB[row][cc]     = __floats2half2_rn(v.x, v.y);
            *(__half2*)&sB[row][cc + 2] = __floats2half2_rn(v.z, v.w);
        }
        __syncthreads();

#pragma unroll
        for (int ks = 0; ks < 64; ks += 16) {
            wmma::fragment<wmma::matrix_a, 16, 16, 16, __half, wmma::row_major> fa;
            wmma::load_matrix_sync(fa, &sA[w * 16][ks], 72);
#pragma unroll
            for (int nt = 0; nt < 4; nt++) {
                wmma::fragment<wmma::matrix_b, 16, 16, 16, __half, wmma::row_major> fb;
                wmma::load_matrix_sync(fb, &sB[ks][nt * 16], 72);
                wmma::mma_sync(acc[nt], fa, fb, acc[nt]);
            }
        }
        __syncthreads();
    }

#pragma unroll
    for (int nt = 0; nt < 4; nt++)
        wmma::store_matrix_sync(&sO[w * 16][nt * 16], acc[nt], 64, wmma::mem_row_major);
    __syncwarp();

#pragma unroll
    for (int q = 0; q < 4; q++) {
        int idx = lane + q * 32;
        int r = idx >> 3;
        int c8 = idx & 7;
        int row = rb + w * 16 + r;
        if (row < N) {
            const float* p = &sO[w * 16 + r][c8 * 8];
            __half2 h0 = __floats2half2_rn(p[0], p[1]);
            __half2 h1 = __floats2half2_rn(p[2], p[3]);
            __half2 h2 = __floats2half2_rn(p[4], p[5]);
            __half2 h3 = __floats2half2_rn(p[6], p[7]);
            uint4 o;
            o.x = *(unsigned*)&h0; o.y = *(unsigned*)&h1;
            o.z = *(unsigned*)&h2; o.w = *(unsigned*)&h3;
            outh[(size_t)row * 8 + c8] = o;
        }
    }
}

// ---------------------------------------------------------------------------
// CSR build
// ---------------------------------------------------------------------------
// Histogram: two coalesced edge streams per thread; all work gated by
// e < half so no thread can double-process an edge.
__global__ void __launch_bounds__(256) hist_kernel(
        const int* __restrict__ dst, int* __restrict__ cnt, int E, int half) {
    int e = blockIdx.x * blockDim.x + threadIdx.x;
    if (e < half) {
        atomicAdd(&cnt[dst[e]], 1);
        int e2 = e + half;
        if (e2 < E) atomicAdd(&cnt[dst[e2]], 1);
    }
}

// Fused exclusive scan with decoupled lookback (98 blocks). Also initializes
// the permute cursor. Deadlock-free: blocks only wait on lower block ids.
__global__ void __launch_bounds__(1024) scan_fused(
        const int* __restrict__ cnt,
        int* __restrict__ off,
        int* __restrict__ cursor,
        volatile int* __restrict__ aggp,   // zeroed before launch; agg+1
        int n, int E) {
    __shared__ int s[1024];
    __shared__ int s_prefix;
    int b = blockIdx.x;
    int i = b * 1024 + threadIdx.x;
    int v = (i < n) ? cnt[i] : 0;
    s[threadIdx.x] = v;
    __syncthreads();
#pragma unroll
    for (int d = 1; d < 1024; d <<= 1) {
        int t = (threadIdx.x >= d) ? s[threadIdx.x - d] : 0;
        __syncthreads();
        s[threadIdx.x] += t;
        __syncthreads();
    }
    int local_excl = s[threadIdx.x] - v;
    int total = s[1023];

    if (threadIdx.x == 0) {
        __threadfence();
        aggp[b] = total + 1;
    }

    int contrib = 0;
    if (threadIdx.x < (unsigned)b) {
        int a;
        do { a = aggp[threadIdx.x]; } while (a == 0);
        contrib = a - 1;
    }
    __syncthreads();
    s[threadIdx.x] = contrib;
    __syncthreads();
#pragma unroll
    for (int d = 512; d; d >>= 1) {
        if (threadIdx.x < d) s[threadIdx.x] += s[threadIdx.x + d];
        __syncthreads();
    }
    if (threadIdx.x == 0) s_prefix = s[0];
    __syncthreads();
    int prefix = s_prefix;

    if (i < n) {
        int o = local_excl + prefix;
        off[i] = o;
        cursor[i] = o;
    }
    if (i == 0) off[n] = E;
}

// Four independent edge chains per thread (quarter-strided, each stream
// coalesced). ALL chains gated by g < quart: a thread outside the base
// range must do nothing, otherwise edges get double-processed (R12 bug —
// cursor atomics are not idempotent).
__global__ void __launch_bounds__(256) permute_kernel(
        const int* __restrict__ src,
        const int* __restrict__ dst,
        const float* __restrict__ ew,
        int* __restrict__ cursor,
        int2* __restrict__ csr, int E, int quart) {
    int g = blockIdx.x * blockDim.x + threadIdx.x;
    if (g >= quart) return;
    int e0 = g;
    int e1 = g + quart;
    int e2 = g + 2 * quart;
    int e3 = g + 3 * quart;
    bool v1 = e1 < E;
    bool v2 = e2 < E;
    bool v3 = e3 < E;
    int d0 = dst[e0];
    int d1 = v1 ? dst[e1] : 0;
    int d2 = v2 ? dst[e2] : 0;
    int d3 = v3 ? dst[e3] : 0;
    int s0 = src[e0];
    int s1 = v1 ? src[e1] : 0;
    int s2 = v2 ? src[e2] : 0;
    int s3 = v3 ? src[e3] : 0;
    float w0 = ew[e0];
    float w1 = v1 ? ew[e1] : 0.f;
    float w2 = v2 ? ew[e2] : 0.f;
    float w3 = v3 ? ew[e3] : 0.f;
    int p0 = atomicAdd(&cursor[d0], 1);
    int p1 = v1 ? atomicAdd(&cursor[d1], 1) : 0;
    int p2 = v2 ? atomicAdd(&cursor[d2], 1) : 0;
    int p3 = v3 ? atomicAdd(&cursor[d3], 1) : 0;
    csr[p0] = make_int2(s0, __float_as_int(w0));
    if (v1) csr[p1] = make_int2(s1, __float_as_int(w1));
    if (v2) csr[p2] = make_int2(s2, __float_as_int(w2));
    if (v3) csr[p3] = make_int2(s3, __float_as_int(w3));
}

// ---------------------------------------------------------------------------
// Gather stage 1 (fused): aggregate fp16 rows of sup1 per node, then
// h = relu(agg + b1), sup2 = fp16(h @ W2). Warp/node, 8-deep MLP.
// Projection via per-warp smem row: 32 LDS + 32 FMA + 1 shfl.
// ---------------------------------------------------------------------------
__global__ void __launch_bounds__(256) gather1_kernel(
        const int* __restrict__ off,
        const int2* __restrict__ csr,
        const unsigned* __restrict__ suph,   // N x 32 half2 words
        const float* __restrict__ b1,
        const float* __restrict__ W2,
        __half* __restrict__ sup2h, int N) {
    __shared__ float sW[NHID * NCLASS];  // 4 KB
    __shared__ float sb[NHID];
    __shared__ float sh[8][NHID];        // per-warp h row
    for (int i = threadIdx.x; i < NHID * NCLASS; i += blockDim.x) sW[i] = W2[i];
    if (threadIdx.x < NHID) sb[threadIdx.x] = b1[threadIdx.x];
    __syncthreads();

    int warp = (blockIdx.x * blockDim.x + threadIdx.x) >> 5;
    int wid = (threadIdx.x >> 5);
    int lane = threadIdx.x & 31;
    if (warp >= N) return;

    int beg = off[warp], end = off[warp + 1];
    float ax = 0.f, ay = 0.f;
    int j = beg;
    for (; j + 8 <= end; j += 8) {
        int2 e[8];
        unsigned u[8];
#pragma unroll
        for (int q = 0; q < 8; q++) e[q] = csr[j + q];
#pragma unroll
        for (int q = 0; q < 8; q++) u[q] = suph[(size_t)e[q].x * 32 + lane];
#pragma unroll
        for (int q = 0; q < 8; q++) {
            float w = __int_as_float(e[q].y);
            float2 f = __half22float2(*(__half2*)&u[q]);
            ax += w * f.x;
            ay += w * f.y;
        }
    }
    for (; j + 2 <= end; j += 2) {
        int2 e0 = csr[j], e1 = csr[j + 1];
        unsigned u0 = suph[(size_t)e0.x * 32 + lane];
        unsigned u1 = suph[(size_t)e1.x * 32 + lane];
        float w0 = __int_as_float(e0.y), w1 = __int_as_float(e1.y);
        float2 f0 = __half22float2(*(__half2*)&u0);
        float2 f1 = __half22float2(*(__half2*)&u1);
        ax += w0 * f0.x + w1 * f1.x;
        ay += w0 * f0.y + w1 * f1.y;
    }
    if (j < end) {
        int2 ed = csr[j];
        float w = __int_as_float(ed.y);
        unsigned u = suph[(size_t)ed.x * 32 + lane];
        float2 f = __half22float2(*(__half2*)&u);
        ax += w * f.x;
        ay += w * f.y;
    }
    sh[wid][2 * lane]     = fmaxf(ax + sb[2 * lane], 0.f);
    sh[wid][2 * lane + 1] = fmaxf(ay + sb[2 * lane + 1], 0.f);
    __syncwarp();

    int c = lane & 15;
    int kh = lane >> 4;
    float acc = 0.f;
#pragma unroll
    for (int i = 0; i < 32; i++) {
        int k = 2 * i + kh;
        acc += sh[wid][k] * sW[k * NCLASS + c];
    }
    acc += __shfl_down_sync(0xffffffffu, acc, 16);
    if (lane < 16) sup2h[(size_t)warp * NCLASS + lane] = __float2half_rn(acc);
}

// ---------------------------------------------------------------------------
// Gather stage 2 (fused): aggregate fp16 sup2 rows, +b2, log_softmax.
// Half-warp per edge slot, unrolled x2 -> 4 edges/warp in flight.
// ---------------------------------------------------------------------------
__global__ void __launch_bounds__(256) gather2_kernel(
        const int* __restrict__ off,
        const int2* __restrict__ csr,
        const __half* __restrict__ sup2h,
        const float* __restrict__ b2,
        float* __restrict__ out, int N) {
    int warp = (blockIdx.x * blockDim.x + threadIdx.x) >> 5;
    int lane = threadIdx.x & 31;
    if (warp >= N) return;
    int l16 = lane & 15;
    int half = lane >> 4;

    int beg = off[warp], end = off[warp + 1];
    float acc = 0.f;
    int j = beg + half;
    for (; j + 2 < end; j += 4) {
        int2 ea = csr[j];
        int2 eb = csr[j + 2];
        float va = __half2float(sup2h[(size_t)ea.x * NCLASS + l16]);
        float vb = __half2float(sup2h[(size_t)eb.x * NCLASS + l16]);
        acc += __int_as_float(ea.y) * va + __int_as_float(eb.y) * vb;
    }
    for (; j < end; j += 2) {
        int2 ed = csr[j];
        acc += __int_as_float(ed.y) * __half2float(sup2h[(size_t)ed.x * NCLASS + l16]);
    }
    acc += __shfl_down_sync(0xffffffffu, acc, 16);

    float v = acc + b2[l16];
    float m = v;
#pragma unroll
    for (int d = 8; d; d >>= 1) m = fmaxf(m, __shfl_xor_sync(0xffffffffu, m, d));
    float ex = expf(v - m);
    float ssum = ex;
#pragma unroll
    for (int d = 8; d; d >>= 1) ssum += __shfl_xor_sync(0xffffffffu, ssum, d);
    float r = v - m - logf(ssum);
    if (lane < 16) out[(size_t)warp * NCLASS + lane] = r;
}

extern "C" void kernel_launch(void* const* d_in, const int* in_sizes, int n_in,
                              void* d_out, int out_size) {
    const float* x  = (const float*)d_in[0];
    const int*   src = (const int*)d_in[1];
    const int*   dst = (const int*)d_in[2];
    const float* ew  = (const float*)d_in[3];
    const float* W1  = (const float*)d_in[4];
    const float* b1  = (const float*)d_in[5];
    const float* W2  = (const float*)d_in[6];
    const float* b2  = (const float*)d_in[7];
    float* out = (float*)d_out;

    int N = in_sizes[0] / NFEAT;   // 100000
    int E = in_sizes[1];           // 1600000

    void *p_sup1h, *p_sup2h, *p_cnt, *p_off, *p_csr, *p_agg;
    cudaGetSymbolAddress(&p_sup1h, g_sup1h);
    cudaGetSymbolAddress(&p_sup2h, g_sup2h);
    cudaGetSymbolAddress(&p_cnt, g_cnt);
    cudaGetSymbolAddress(&p_off, g_off);
    cudaGetSymbolAddress(&p_csr, g_csr);
    cudaGetSymbolAddress(&p_agg, g_agg);

    int nb_scan = (N + 1023) / 1024;   // 98

    // Fork: gemm1 on a side stream, overlapped with the CSR build.
    cudaStream_t s1;
    cudaStreamCreateWithFlags(&s1, cudaStreamNonBlocking);
    cudaEvent_t e0, e1;
    cudaEventCreateWithFlags(&e0, cudaEventDisableTiming);
    cudaEventCreateWithFlags(&e1, cudaEventDisableTiming);

    cudaEventRecord(e0, 0);
    cudaStreamWaitEvent(s1, e0, 0);
    gemm1_kernel<<<(N + 127) / 128, 256, 0, s1>>>(x, W1, (uint4*)p_sup1h, N);
    cudaEventRecord(e1, s1);

    // --- CSR build (main stream) ---
    cudaMemsetAsync(p_cnt, 0, (size_t)N * sizeof(int));
    cudaMemsetAsync(p_agg, 0, 128 * sizeof(int));
    {
        int half = (E + 1) / 2;
        int blocks = (half + 255) / 256;
        hist_kernel<<<blocks, 256>>>(dst, (int*)p_cnt, E, half);
    }
    scan_fused<<<nb_scan, 1024>>>((const int*)p_cnt, (int*)p_off, (int*)p_cnt,
                                  (volatile int*)p_agg, N, E);
    {
        int quart = (E + 3) / 4;
        int blocks = (quart + 255) / 256;
        permute_kernel<<<blocks, 256>>>(src, dst, ew, (int*)p_cnt,
                                        (int2*)p_csr, E, quart);
    }

    // Join: gathers need both CSR and sup1.
    cudaStreamWaitEvent(0, e1, 0);

    gather1_kernel<<<(N * 32 + 255) / 256, 256>>>(
        (const int*)p_off, (const int2*)p_csr, (const unsigned*)p_sup1h,
        b1, W2, (__half*)p_sup2h, N);

    gather2_kernel<<<(N * 32 + 255) / 256, 256>>>(
        (const int*)p_off, (const int2*)p_csr, (const __half*)p_sup2h,
        b2, out, N);
}

// round 14
// speedup vs baseline: 1.0706x; 1.0232x over previous
#include <cuda_runtime.h>
#include <cuda_fp16.h>
#include <cuda_bf16.h>
#include <mma.h>
#include <math.h>

using namespace nvcuda;

// Problem constants (fixed by the dataset)
#define NNODES 100000
#define MAXE   1600000
#define NFEAT  128
#define NHID   64
#define NCLASS 16

// Scratch buffers.
__device__ __align__(128) uint4  g_sup1h[NNODES * 8];   // N x 64 fp16 (x @ W1)
__device__ __align__(128) __half g_sup2h[NNODES * 16];  // N x 16 fp16 (h @ W2)
__device__ int  g_cnt[NNODES];       // degree counts, then permute cursor
__device__ int  g_off[NNODES + 1];   // CSR offsets
__device__ int2 g_csr[MAXE];         // packed {src, float_as_int(w)}
__device__ int  g_agg[128];          // scan lookback aggregates; memset per call

// ---------------------------------------------------------------------------
// GEMM1 (HMMA): sup1[N,64] = x[N,128] @ W1[128,64], fp16 in, fp32 acc,
// fp16 out. 128x64 block tile, KC=64 (2 phases), 8 warps, warp = 16 rows.
// ---------------------------------------------------------------------------
__global__ void __launch_bounds__(256) gemm1_kernel(
        const float* __restrict__ x,
        const float* __restrict__ W1,
        uint4* __restrict__ outh, int N) {
    __shared__ __align__(16) char smem[32768];
    __half (*sA)[72] = (__half(*)[72])smem;                  // 128 x 72 halves
    __half (*sB)[72] = (__half(*)[72])(smem + 128 * 72 * 2); // 64 x 72 halves
    float (*sO)[64]  = (float(*)[64])smem;                   // epilogue alias

    int tid = threadIdx.x;
    int w = tid >> 5;
    int lane = tid & 31;
    int rb = blockIdx.x * 128;

    wmma::fragment<wmma::accumulator, 16, 16, 16, float> acc[4];
#pragma unroll
    for (int i = 0; i < 4; i++) wmma::fill_fragment(acc[i], 0.f);

#pragma unroll
    for (int kb = 0; kb < NFEAT; kb += 64) {
#pragma unroll
        for (int it = 0; it < 8; it++) {
            int idx = tid + it * 256;
            int row = idx >> 4;
            int cc = (idx & 15) * 4;
            float4 v = make_float4(0.f, 0.f, 0.f, 0.f);
            if (rb + row < N)
                v = *(const float4*)&x[(size_t)(rb + row) * NFEAT + kb + cc];
            *(__half2*)&sA[row][cc]     = __floats2half2_rn(v.x, v.y);
            *(__half2*)&sA[row][cc + 2] = __floats2half2_rn(v.z, v.w);
        }
#pragma unroll
        for (int it = 0; it < 4; it++) {
            int idx = tid + it * 256;
            int row = idx >> 4;
            int cc = (idx & 15) * 4;
            float4 v = *(const float4*)&W1[(size_t)(kb + row) * NHID + cc];
            *(__half2*)&sB[row][cc]     = __floats2half2_rn(v.x, v.y);
            *(__half2*)&sB[row][cc + 2] = __floats2half2_rn(v.z, v.w);
        }
        __syncthreads();

#pragma unroll
        for (int ks = 0; ks < 64; ks += 16) {
            wmma::fragment<wmma::matrix_a, 16, 16, 16, __half, wmma::row_major> fa;
            wmma::load_matrix_sync(fa, &sA[w * 16][ks], 72);
#pragma unroll
            for (int nt = 0; nt < 4; nt++) {
                wmma::fragment<wmma::matrix_b, 16, 16, 16, __half, wmma::row_major> fb;
                wmma::load_matrix_sync(fb, &sB[ks][nt * 16], 72);
                wmma::mma_sync(acc[nt], fa, fb, acc[nt]);
            }
        }
        __syncthreads();
    }

#pragma unroll
    for (int nt = 0; nt < 4; nt++)
        wmma::store_matrix_sync(&sO[w * 16][nt * 16], acc[nt], 64, wmma::mem_row_major);
    __syncwarp();

#pragma unroll
    for (int q = 0; q < 4; q++) {
        int idx = lane + q * 32;
        int r = idx >> 3;
        int c8 = idx & 7;
        int row = rb + w * 16 + r;
        if (row < N) {
            const float* p = &sO[w * 16 + r][c8 * 8];
            __half2 h0 = __floats2half2_rn(p[0], p[1]);
            __half2 h1 = __floats2half2_rn(p[2], p[3]);
            __half2 h2 = __floats2half2_rn(p[4], p[5]);
            __half2 h3 = __floats2half2_rn(p[6], p[7]);
            uint4 o;
            o.x = *(unsigned*)&h0; o.y = *(unsigned*)&h1;
            o.z = *(unsigned*)&h2; o.w = *(unsigned*)&h3;
            outh[(size_t)row * 8 + c8] = o;
        }
    }
}

// ---------------------------------------------------------------------------
// CSR build
// ---------------------------------------------------------------------------
__global__ void hist_kernel(const int* __restrict__ dst, int* __restrict__ cnt, int E) {
    int e = blockIdx.x * blockDim.x + threadIdx.x;
    if (e < E) atomicAdd(&cnt[dst[e]], 1);
}

// Fused exclusive scan with decoupled lookback (98 blocks). Also initializes
// the permute cursor. PDL consumer of hist: grid-sync before reading cnt.
__global__ void __launch_bounds__(1024) scan_fused(
        const int* __restrict__ cnt,
        int* __restrict__ off,
        int* __restrict__ cursor,
        volatile int* __restrict__ aggp,   // zeroed before launch; agg+1
        int n, int E) {
    cudaGridDependencySynchronize();       // wait for hist's cnt
    __shared__ int s[1024];
    __shared__ int s_prefix;
    int b = blockIdx.x;
    int i = b * 1024 + threadIdx.x;
    int v = (i < n) ? cnt[i] : 0;
    s[threadIdx.x] = v;
    __syncthreads();
#pragma unroll
    for (int d = 1; d < 1024; d <<= 1) {
        int t = (threadIdx.x >= d) ? s[threadIdx.x - d] : 0;
        __syncthreads();
        s[threadIdx.x] += t;
        __syncthreads();
    }
    int local_excl = s[threadIdx.x] - v;
    int total = s[1023];

    if (threadIdx.x == 0) {
        __threadfence();
        aggp[b] = total + 1;
    }

    int contrib = 0;
    if (threadIdx.x < (unsigned)b) {
        int a;
        do { a = aggp[threadIdx.x]; } while (a == 0);
        contrib = a - 1;
    }
    __syncthreads();
    s[threadIdx.x] = contrib;
    __syncthreads();
#pragma unroll
    for (int d = 512; d; d >>= 1) {
        if (threadIdx.x < d) s[threadIdx.x] += s[threadIdx.x + d];
        __syncthreads();
    }
    if (threadIdx.x == 0) s_prefix = s[0];
    __syncthreads();
    int prefix = s_prefix;

    if (i < n) {
        int o = local_excl + prefix;
        off[i] = o;
        cursor[i] = o;
    }
    if (i == 0) off[n] = E;
}

// Two independent edge chains per thread. PDL consumer of scan: loads its
// dependency-free inputs (src/dst/ew) BEFORE the grid-sync, overlapping the
// producer's tail; cursor atomics only after the sync.
__global__ void __launch_bounds__(256) permute_kernel(
        const int* __restrict__ src,
        const int* __restrict__ dst,
        const float* __restrict__ ew,
        int* __restrict__ cursor,
        int2* __restrict__ csr, int E, int half) {
    int g = blockIdx.x * blockDim.x + threadIdx.x;
    int e0 = g;
    int e1 = g + half;
    bool v0 = e0 < half;
    bool v1 = e1 < E;
    int d0 = v0 ? dst[e0] : 0;
    int d1 = v1 ? dst[e1] : 0;
    int s0 = v0 ? src[e0] : 0;
    int s1 = v1 ? src[e1] : 0;
    float w0 = v0 ? ew[e0] : 0.f;
    float w1 = v1 ? ew[e1] : 0.f;
    cudaGridDependencySynchronize();       // wait for scan's cursor/off
    int p0 = v0 ? atomicAdd(&cursor[d0], 1) : 0;
    int p1 = v1 ? atomicAdd(&cursor[d1], 1) : 0;
    if (v0) csr[p0] = make_int2(s0, __float_as_int(w0));
    if (v1) csr[p1] = make_int2(s1, __float_as_int(w1));
}

// ---------------------------------------------------------------------------
// Gather stage 1 (fused): aggregate fp16 rows of sup1 per node, then
// h = relu(agg + b1), sup2 = fp16(h @ W2). Warp/node, 8-deep MLP.
// Projection via per-warp smem row: 32 LDS + 32 FMA + 1 shfl.
// ---------------------------------------------------------------------------
__global__ void __launch_bounds__(256) gather1_kernel(
        const int* __restrict__ off,
        const int2* __restrict__ csr,
        const unsigned* __restrict__ suph,   // N x 32 half2 words
        const float* __restrict__ b1,
        const float* __restrict__ W2,
        __half* __restrict__ sup2h, int N) {
    __shared__ float sW[NHID * NCLASS];  // 4 KB
    __shared__ float sb[NHID];
    __shared__ float sh[8][NHID];        // per-warp h row
    for (int i = threadIdx.x; i < NHID * NCLASS; i += blockDim.x) sW[i] = W2[i];
    if (threadIdx.x < NHID) sb[threadIdx.x] = b1[threadIdx.x];
    __syncthreads();

    int warp = (blockIdx.x * blockDim.x + threadIdx.x) >> 5;
    int wid = (threadIdx.x >> 5);
    int lane = threadIdx.x & 31;
    if (warp >= N) return;

    int beg = off[warp], end = off[warp + 1];
    float ax = 0.f, ay = 0.f;
    int j = beg;
    for (; j + 8 <= end; j += 8) {
        int2 e[8];
        unsigned u[8];
#pragma unroll
        for (int q = 0; q < 8; q++) e[q] = csr[j + q];
#pragma unroll
        for (int q = 0; q < 8; q++) u[q] = suph[(size_t)e[q].x * 32 + lane];
#pragma unroll
        for (int q = 0; q < 8; q++) {
            float w = __int_as_float(e[q].y);
            float2 f = __half22float2(*(__half2*)&u[q]);
            ax += w * f.x;
            ay += w * f.y;
        }
    }
    for (; j + 2 <= end; j += 2) {
        int2 e0 = csr[j], e1 = csr[j + 1];
        unsigned u0 = suph[(size_t)e0.x * 32 + lane];
        unsigned u1 = suph[(size_t)e1.x * 32 + lane];
        float w0 = __int_as_float(e0.y), w1 = __int_as_float(e1.y);
        float2 f0 = __half22float2(*(__half2*)&u0);
        float2 f1 = __half22float2(*(__half2*)&u1);
        ax += w0 * f0.x + w1 * f1.x;
        ay += w0 * f0.y + w1 * f1.y;
    }
    if (j < end) {
        int2 ed = csr[j];
        float w = __int_as_float(ed.y);
        unsigned u = suph[(size_t)ed.x * 32 + lane];
        float2 f = __half22float2(*(__half2*)&u);
        ax += w * f.x;
        ay += w * f.y;
    }
    sh[wid][2 * lane]     = fmaxf(ax + sb[2 * lane], 0.f);
    sh[wid][2 * lane + 1] = fmaxf(ay + sb[2 * lane + 1], 0.f);
    __syncwarp();

    int c = lane & 15;
    int kh = lane >> 4;
    float acc = 0.f;
#pragma unroll
    for (int i = 0; i < 32; i++) {
        int k = 2 * i + kh;
        acc += sh[wid][k] * sW[k * NCLASS + c];
    }
    acc += __shfl_down_sync(0xffffffffu, acc, 16);
    if (lane < 16) sup2h[(size_t)warp * NCLASS + lane] = __float2half_rn(acc);
}

// ---------------------------------------------------------------------------
// Gather stage 2 (fused): aggregate fp16 sup2 rows, +b2, log_softmax.
// PDL consumer of gather1: grid-sync before reading sup2h.
// ---------------------------------------------------------------------------
__global__ void __launch_bounds__(256) gather2_kernel(
        const int* __restrict__ off,
        const int2* __restrict__ csr,
        const __half* __restrict__ sup2h,
        const float* __restrict__ b2,
        float* __restrict__ out, int N) {
    cudaGridDependencySynchronize();       // wait for gather1's sup2h
    int warp = (blockIdx.x * blockDim.x + threadIdx.x) >> 5;
    int lane = threadIdx.x & 31;
    if (warp >= N) return;
    int l16 = lane & 15;
    int half = lane >> 4;

    int beg = off[warp], end = off[warp + 1];
    float acc = 0.f;
    int j = beg + half;
    for (; j + 2 < end; j += 4) {
        int2 ea = csr[j];
        int2 eb = csr[j + 2];
        float va = __half2float(sup2h[(size_t)ea.x * NCLASS + l16]);
        float vb = __half2float(sup2h[(size_t)eb.x * NCLASS + l16]);
        acc += __int_as_float(ea.y) * va + __int_as_float(eb.y) * vb;
    }
    for (; j < end; j += 2) {
        int2 ed = csr[j];
        acc += __int_as_float(ed.y) * __half2float(sup2h[(size_t)ed.x * NCLASS + l16]);
    }
    acc += __shfl_down_sync(0xffffffffu, acc, 16);

    float v = acc + b2[l16];
    float m = v;
#pragma unroll
    for (int d = 8; d; d >>= 1) m = fmaxf(m, __shfl_xor_sync(0xffffffffu, m, d));
    float ex = expf(v - m);
    float ssum = ex;
#pragma unroll
    for (int d = 8; d; d >>= 1) ssum += __shfl_xor_sync(0xffffffffu, ssum, d);
    float r = v - m - logf(ssum);
    if (lane < 16) out[(size_t)warp * NCLASS + lane] = r;
}

extern "C" void kernel_launch(void* const* d_in, const int* in_sizes, int n_in,
                              void* d_out, int out_size) {
    const float* x  = (const float*)d_in[0];
    const int*   src = (const int*)d_in[1];
    const int*   dst = (const int*)d_in[2];
    const float* ew  = (const float*)d_in[3];
    const float* W1  = (const float*)d_in[4];
    const float* b1  = (const float*)d_in[5];
    const float* W2  = (const float*)d_in[6];
    const float* b2  = (const float*)d_in[7];
    float* out = (float*)d_out;

    int N = in_sizes[0] / NFEAT;   // 100000
    int E = in_sizes[1];           // 1600000

    void *p_sup1h, *p_sup2h, *p_cnt, *p_off, *p_csr, *p_agg;
    cudaGetSymbolAddress(&p_sup1h, g_sup1h);
    cudaGetSymbolAddress(&p_sup2h, g_sup2h);
    cudaGetSymbolAddress(&p_cnt, g_cnt);
    cudaGetSymbolAddress(&p_off, g_off);
    cudaGetSymbolAddress(&p_csr, g_csr);
    cudaGetSymbolAddress(&p_agg, g_agg);

    int nb_scan = (N + 1023) / 1024;   // 98

    // PDL launch config (programmatic stream serialization).
    cudaLaunchAttribute pdl_attr[1];
    pdl_attr[0].id = cudaLaunchAttributeProgrammaticStreamSerialization;
    pdl_attr[0].val.programmaticStreamSerializationAllowed = 1;

    // Fork: gemm1 on a side stream, overlapped with the CSR build.
    cudaStream_t s1;
    cudaStreamCreateWithFlags(&s1, cudaStreamNonBlocking);
    cudaEvent_t e0, e1;
    cudaEventCreateWithFlags(&e0, cudaEventDisableTiming);
    cudaEventCreateWithFlags(&e1, cudaEventDisableTiming);

    cudaEventRecord(e0, 0);
    cudaStreamWaitEvent(s1, e0, 0);
    gemm1_kernel<<<(N + 127) / 128, 256, 0, s1>>>(x, W1, (uint4*)p_sup1h, N);
    cudaEventRecord(e1, s1);

    // --- CSR build (main stream) ---
    cudaMemsetAsync(p_cnt, 0, (size_t)N * sizeof(int));
    cudaMemsetAsync(p_agg, 0, 128 * sizeof(int));
    hist_kernel<<<(E + 255) / 256, 256>>>(dst, (int*)p_cnt, E);
    {
        // scan: PDL consumer of hist
        cudaLaunchConfig_t cfg = {};
        cfg.gridDim = dim3(nb_scan);
        cfg.blockDim = dim3(1024);
        cfg.stream = 0;
        cfg.attrs = pdl_attr;
        cfg.numAttrs = 1;
        cudaLaunchKernelEx(&cfg, scan_fused,
                           (const int*)p_cnt, (int*)p_off, (int*)p_cnt,
                           (volatile int*)p_agg, N, E);
    }
    {
        // permute: PDL consumer of scan
        int half = (E + 1) / 2;
        int blocks = (half + 255) / 256;
        cudaLaunchConfig_t cfg = {};
        cfg.gridDim = dim3(blocks);
        cfg.blockDim = dim3(256);
        cfg.stream = 0;
        cfg.attrs = pdl_attr;
        cfg.numAttrs = 1;
        cudaLaunchKernelEx(&cfg, permute_kernel,
                           src, dst, ew, (int*)p_cnt, (int2*)p_csr, E, half);
    }

    // Join: gathers need both CSR and sup1 (normal launch after event wait).
    cudaStreamWaitEvent(0, e1, 0);

    gather1_kernel<<<(N * 32 + 255) / 256, 256>>>(
        (const int*)p_off, (const int2*)p_csr, (const unsigned*)p_sup1h,
        b1, W2, (__half*)p_sup2h, N);

    {
        // gather2: PDL consumer of gather1
        int blocks = (N * 32 + 255) / 256;
        cudaLaunchConfig_t cfg = {};
        cfg.gridDim = dim3(blocks);
        cfg.blockDim = dim3(256);
        cfg.stream = 0;
        cfg.attrs = pdl_attr;
        cfg.numAttrs = 1;
        cudaLaunchKernelEx(&cfg, gather2_kernel,
                           (const int*)p_off, (const int2*)p_csr,
                           (const __half*)p_sup2h, b2, out, N);
    }
}

// round 15
// speedup vs baseline: 1.0833x; 1.0119x over previous
#include <cuda_runtime.h>
#include <cuda_fp16.h>
#include <cuda_bf16.h>
#include <mma.h>
#include <math.h>

using namespace nvcuda;

// Problem constants (fixed by the dataset)
#define NNODES 100000
#define MAXE   1600000
#define NFEAT  128
#define NHID   64
#define NCLASS 16

// Scratch buffers.
__device__ __align__(128) uint4  g_sup1h[NNODES * 8];   // N x 64 fp16 (x @ W1)
__device__ __align__(128) __half g_sup2h[NNODES * 16];  // N x 16 fp16 (h @ W2)
__device__ int  g_cnt[NNODES];       // degree counts, then permute cursor
__device__ int  g_off[NNODES + 1];   // CSR offsets
__device__ int2 g_csr[MAXE];         // packed {src, float_as_int(w)}
__device__ int  g_agg[128];          // scan lookback aggregates; memset per call

// ---------------------------------------------------------------------------
// GEMM1 (HMMA): sup1[N,64] = x[N,128] @ W1[128,64], fp16 in, fp32 acc,
// fp16 out. 128x64 block tile, KC=64 (2 phases), 8 warps, warp = 16 rows.
// ---------------------------------------------------------------------------
__global__ void __launch_bounds__(256) gemm1_kernel(
        const float* __restrict__ x,
        const float* __restrict__ W1,
        uint4* __restrict__ outh, int N) {
    __shared__ __align__(16) char smem[32768];
    __half (*sA)[72] = (__half(*)[72])smem;                  // 128 x 72 halves
    __half (*sB)[72] = (__half(*)[72])(smem + 128 * 72 * 2); // 64 x 72 halves
    float (*sO)[64]  = (float(*)[64])smem;                   // epilogue alias

    int tid = threadIdx.x;
    int w = tid >> 5;
    int lane = tid & 31;
    int rb = blockIdx.x * 128;

    wmma::fragment<wmma::accumulator, 16, 16, 16, float> acc[4];
#pragma unroll
    for (int i = 0; i < 4; i++) wmma::fill_fragment(acc[i], 0.f);

#pragma unroll
    for (int kb = 0; kb < NFEAT; kb += 64) {
#pragma unroll
        for (int it = 0; it < 8; it++) {
            int idx = tid + it * 256;
            int row = idx >> 4;
            int cc = (idx & 15) * 4;
            float4 v = make_float4(0.f, 0.f, 0.f, 0.f);
            if (rb + row < N)
                v = *(const float4*)&x[(size_t)(rb + row) * NFEAT + kb + cc];
            *(__half2*)&sA[row][cc]     = __floats2half2_rn(v.x, v.y);
            *(__half2*)&sA[row][cc + 2] = __floats2half2_rn(v.z, v.w);
        }
#pragma unroll
        for (int it = 0; it < 4; it++) {
            int idx = tid + it * 256;
            int row = idx >> 4;
            int cc = (idx & 15) * 4;
            float4 v = *(const float4*)&W1[(size_t)(kb + row) * NHID + cc];
            *(__half2*)&sB[row][cc]     = __floats2half2_rn(v.x, v.y);
            *(__half2*)&sB[row][cc + 2] = __floats2half2_rn(v.z, v.w);
        }
        __syncthreads();

#pragma unroll
        for (int ks = 0; ks < 64; ks += 16) {
            wmma::fragment<wmma::matrix_a, 16, 16, 16, __half, wmma::row_major> fa;
            wmma::load_matrix_sync(fa, &sA[w * 16][ks], 72);
#pragma unroll
            for (int nt = 0; nt < 4; nt++) {
                wmma::fragment<wmma::matrix_b, 16, 16, 16, __half, wmma::row_major> fb;
                wmma::load_matrix_sync(fb, &sB[ks][nt * 16], 72);
                wmma::mma_sync(acc[nt], fa, fb, acc[nt]);
            }
        }
        __syncthreads();
    }

#pragma unroll
    for (int nt = 0; nt < 4; nt++)
        wmma::store_matrix_sync(&sO[w * 16][nt * 16], acc[nt], 64, wmma::mem_row_major);
    __syncwarp();

#pragma unroll
    for (int q = 0; q < 4; q++) {
        int idx = lane + q * 32;
        int r = idx >> 3;
        int c8 = idx & 7;
        int row = rb + w * 16 + r;
        if (row < N) {
            const float* p = &sO[w * 16 + r][c8 * 8];
            __half2 h0 = __floats2half2_rn(p[0], p[1]);
            __half2 h1 = __floats2half2_rn(p[2], p[3]);
            __half2 h2 = __floats2half2_rn(p[4], p[5]);
            __half2 h3 = __floats2half2_rn(p[6], p[7]);
            uint4 o;
            o.x = *(unsigned*)&h0; o.y = *(unsigned*)&h1;
            o.z = *(unsigned*)&h2; o.w = *(unsigned*)&h3;
            outh[(size_t)row * 8 + c8] = o;
        }
    }
}

// ---------------------------------------------------------------------------
// CSR build
// ---------------------------------------------------------------------------
// Histogram: 4 consecutive edges per thread via one LDG.128.
__global__ void __launch_bounds__(256) hist_kernel(
        const int* __restrict__ dst, int* __restrict__ cnt, int E) {
    int e4 = (blockIdx.x * blockDim.x + threadIdx.x) * 4;
    if (e4 + 3 < E) {
        int4 d = *(const int4*)&dst[e4];
        atomicAdd(&cnt[d.x], 1);
        atomicAdd(&cnt[d.y], 1);
        atomicAdd(&cnt[d.z], 1);
        atomicAdd(&cnt[d.w], 1);
    } else {
        for (int e = e4; e < E; e++) atomicAdd(&cnt[dst[e]], 1);
    }
}

// Fused exclusive scan with decoupled lookback (98 blocks). Also initializes
// the permute cursor. Deadlock-free: blocks only wait on lower block ids.
__global__ void __launch_bounds__(1024) scan_fused(
        const int* __restrict__ cnt,
        int* __restrict__ off,
        int* __restrict__ cursor,
        volatile int* __restrict__ aggp,   // zeroed before launch; agg+1
        int n, int E) {
    __shared__ int s[1024];
    __shared__ int s_prefix;
    int b = blockIdx.x;
    int i = b * 1024 + threadIdx.x;
    int v = (i < n) ? cnt[i] : 0;
    s[threadIdx.x] = v;
    __syncthreads();
#pragma unroll
    for (int d = 1; d < 1024; d <<= 1) {
        int t = (threadIdx.x >= d) ? s[threadIdx.x - d] : 0;
        __syncthreads();
        s[threadIdx.x] += t;
        __syncthreads();
    }
    int local_excl = s[threadIdx.x] - v;
    int total = s[1023];

    if (threadIdx.x == 0) {
        __threadfence();
        aggp[b] = total + 1;
    }

    int contrib = 0;
    if (threadIdx.x < (unsigned)b) {
        int a;
        do { a = aggp[threadIdx.x]; } while (a == 0);
        contrib = a - 1;
    }
    __syncthreads();
    s[threadIdx.x] = contrib;
    __syncthreads();
#pragma unroll
    for (int d = 512; d; d >>= 1) {
        if (threadIdx.x < d) s[threadIdx.x] += s[threadIdx.x + d];
        __syncthreads();
    }
    if (threadIdx.x == 0) s_prefix = s[0];
    __syncthreads();
    int prefix = s_prefix;

    if (i < n) {
        int o = local_excl + prefix;
        off[i] = o;
        cursor[i] = o;
    }
    if (i == 0) off[n] = E;
}

// Permute: 4 consecutive edges per thread via 3x LDG.128 (dst/src int4,
// ew float4) -> 4 independent atomic->store chains with coalesced loads.
__global__ void __launch_bounds__(256) permute_kernel(
        const int* __restrict__ src,
        const int* __restrict__ dst,
        const float* __restrict__ ew,
        int* __restrict__ cursor,
        int2* __restrict__ csr, int E) {
    int e4 = (blockIdx.x * blockDim.x + threadIdx.x) * 4;
    if (e4 + 3 < E) {
        int4 d = *(const int4*)&dst[e4];
        int4 s = *(const int4*)&src[e4];
        float4 w = *(const float4*)&ew[e4];
        int p0 = atomicAdd(&cursor[d.x], 1);
        int p1 = atomicAdd(&cursor[d.y], 1);
        int p2 = atomicAdd(&cursor[d.z], 1);
        int p3 = atomicAdd(&cursor[d.w], 1);
        csr[p0] = make_int2(s.x, __float_as_int(w.x));
        csr[p1] = make_int2(s.y, __float_as_int(w.y));
        csr[p2] = make_int2(s.z, __float_as_int(w.z));
        csr[p3] = make_int2(s.w, __float_as_int(w.w));
    } else {
        for (int e = e4; e < E; e++) {
            int p = atomicAdd(&cursor[dst[e]], 1);
            csr[p] = make_int2(src[e], __float_as_int(ew[e]));
        }
    }
}

// ---------------------------------------------------------------------------
// Gather stage 1 (fused): aggregate fp16 rows of sup1 per node, then
// h = relu(agg + b1), sup2 = fp16(h @ W2). Warp/node, 8-deep MLP.
// Projection via per-warp smem row: 32 LDS + 32 FMA + 1 shfl.
// ---------------------------------------------------------------------------
__global__ void __launch_bounds__(256) gather1_kernel(
        const int* __restrict__ off,
        const int2* __restrict__ csr,
        const unsigned* __restrict__ suph,   // N x 32 half2 words
        const float* __restrict__ b1,
        const float* __restrict__ W2,
        __half* __restrict__ sup2h, int N) {
    __shared__ float sW[NHID * NCLASS];  // 4 KB
    __shared__ float sb[NHID];
    __shared__ float sh[8][NHID];        // per-warp h row
    for (int i = threadIdx.x; i < NHID * NCLASS; i += blockDim.x) sW[i] = W2[i];
    if (threadIdx.x < NHID) sb[threadIdx.x] = b1[threadIdx.x];
    __syncthreads();

    int warp = (blockIdx.x * blockDim.x + threadIdx.x) >> 5;
    int wid = (threadIdx.x >> 5);
    int lane = threadIdx.x & 31;
    if (warp >= N) return;

    int beg = off[warp], end = off[warp + 1];
    float ax = 0.f, ay = 0.f;
    int j = beg;
    for (; j + 8 <= end; j += 8) {
        int2 e[8];
        unsigned u[8];
#pragma unroll
        for (int q = 0; q < 8; q++) e[q] = csr[j + q];
#pragma unroll
        for (int q = 0; q < 8; q++) u[q] = suph[(size_t)e[q].x * 32 + lane];
#pragma unroll
        for (int q = 0; q < 8; q++) {
            float w = __int_as_float(e[q].y);
            float2 f = __half22float2(*(__half2*)&u[q]);
            ax += w * f.x;
            ay += w * f.y;
        }
    }
    for (; j + 2 <= end; j += 2) {
        int2 e0 = csr[j], e1 = csr[j + 1];
        unsigned u0 = suph[(size_t)e0.x * 32 + lane];
        unsigned u1 = suph[(size_t)e1.x * 32 + lane];
        float w0 = __int_as_float(e0.y), w1 = __int_as_float(e1.y);
        float2 f0 = __half22float2(*(__half2*)&u0);
        float2 f1 = __half22float2(*(__half2*)&u1);
        ax += w0 * f0.x + w1 * f1.x;
        ay += w0 * f0.y + w1 * f1.y;
    }
    if (j < end) {
        int2 ed = csr[j];
        float w = __int_as_float(ed.y);
        unsigned u = suph[(size_t)ed.x * 32 + lane];
        float2 f = __half22float2(*(__half2*)&u);
        ax += w * f.x;
        ay += w * f.y;
    }
    sh[wid][2 * lane]     = fmaxf(ax + sb[2 * lane], 0.f);
    sh[wid][2 * lane + 1] = fmaxf(ay + sb[2 * lane + 1], 0.f);
    __syncwarp();

    int c = lane & 15;
    int kh = lane >> 4;
    float acc = 0.f;
#pragma unroll
    for (int i = 0; i < 32; i++) {
        int k = 2 * i + kh;
        acc += sh[wid][k] * sW[k * NCLASS + c];
    }
    acc += __shfl_down_sync(0xffffffffu, acc, 16);
    if (lane < 16) sup2h[(size_t)warp * NCLASS + lane] = __float2half_rn(acc);
}

// ---------------------------------------------------------------------------
// Gather stage 2 (fused): aggregate fp16 sup2 rows, +b2, log_softmax.
// Half-warp per edge slot, unrolled x2 -> 4 edges/warp in flight.
// ---------------------------------------------------------------------------
__global__ void __launch_bounds__(256) gather2_kernel(
        const int* __restrict__ off,
        const int2* __restrict__ csr,
        const __half* __restrict__ sup2h,
        const float* __restrict__ b2,
        float* __restrict__ out, int N) {
    int warp = (blockIdx.x * blockDim.x + threadIdx.x) >> 5;
    int lane = threadIdx.x & 31;
    if (warp >= N) return;
    int l16 = lane & 15;
    int half = lane >> 4;

    int beg = off[warp], end = off[warp + 1];
    float acc = 0.f;
    int j = beg + half;
    for (; j + 2 < end; j += 4) {
        int2 ea = csr[j];
        int2 eb = csr[j + 2];
        float va = __half2float(sup2h[(size_t)ea.x * NCLASS + l16]);
        float vb = __half2float(sup2h[(size_t)eb.x * NCLASS + l16]);
        acc += __int_as_float(ea.y) * va + __int_as_float(eb.y) * vb;
    }
    for (; j < end; j += 2) {
        int2 ed = csr[j];
        acc += __int_as_float(ed.y) * __half2float(sup2h[(size_t)ed.x * NCLASS + l16]);
    }
    acc += __shfl_down_sync(0xffffffffu, acc, 16);

    float v = acc + b2[l16];
    float m = v;
#pragma unroll
    for (int d = 8; d; d >>= 1) m = fmaxf(m, __shfl_xor_sync(0xffffffffu, m, d));
    float ex = expf(v - m);
    float ssum = ex;
#pragma unroll
    for (int d = 8; d; d >>= 1) ssum += __shfl_xor_sync(0xffffffffu, ssum, d);
    float r = v - m - logf(ssum);
    if (lane < 16) out[(size_t)warp * NCLASS + lane] = r;
}

extern "C" void kernel_launch(void* const* d_in, const int* in_sizes, int n_in,
                              void* d_out, int out_size) {
    const float* x  = (const float*)d_in[0];
    const int*   src = (const int*)d_in[1];
    const int*   dst = (const int*)d_in[2];
    const float* ew  = (const float*)d_in[3];
    const float* W1  = (const float*)d_in[4];
    const float* b1  = (const float*)d_in[5];
    const float* W2  = (const float*)d_in[6];
    const float* b2  = (const float*)d_in[7];
    float* out = (float*)d_out;

    int N = in_sizes[0] / NFEAT;   // 100000
    int E = in_sizes[1];           // 1600000

    void *p_sup1h, *p_sup2h, *p_cnt, *p_off, *p_csr, *p_agg;
    cudaGetSymbolAddress(&p_sup1h, g_sup1h);
    cudaGetSymbolAddress(&p_sup2h, g_sup2h);
    cudaGetSymbolAddress(&p_cnt, g_cnt);
    cudaGetSymbolAddress(&p_off, g_off);
    cudaGetSymbolAddress(&p_csr, g_csr);
    cudaGetSymbolAddress(&p_agg, g_agg);

    int nb_scan = (N + 1023) / 1024;   // 98

    // Fork: gemm1 on a side stream, overlapped with the CSR build.
    cudaStream_t s1;
    cudaStreamCreateWithFlags(&s1, cudaStreamNonBlocking);
    cudaEvent_t e0, e1;
    cudaEventCreateWithFlags(&e0, cudaEventDisableTiming);
    cudaEventCreateWithFlags(&e1, cudaEventDisableTiming);

    cudaEventRecord(e0, 0);
    cudaStreamWaitEvent(s1, e0, 0);
    gemm1_kernel<<<(N + 127) / 128, 256, 0, s1>>>(x, W1, (uint4*)p_sup1h, N);
    cudaEventRecord(e1, s1);

    // --- CSR build (main stream) ---
    cudaMemsetAsync(p_cnt, 0, (size_t)N * sizeof(int));
    cudaMemsetAsync(p_agg, 0, 128 * sizeof(int));
    {
        int q = (E + 3) / 4;
        hist_kernel<<<(q + 255) / 256, 256>>>(dst, (int*)p_cnt, E);
    }
    scan_fused<<<nb_scan, 1024>>>((const int*)p_cnt, (int*)p_off, (int*)p_cnt,
                                  (volatile int*)p_agg, N, E);
    {
        int q = (E + 3) / 4;
        permute_kernel<<<(q + 255) / 256, 256>>>(src, dst, ew, (int*)p_cnt,
                                                 (int2*)p_csr, E);
    }

    // Join: gathers need both CSR and sup1.
    cudaStreamWaitEvent(0, e1, 0);

    gather1_kernel<<<(N * 32 + 255) / 256, 256>>>(
        (const int*)p_off, (const int2*)p_csr, (const unsigned*)p_sup1h,
        b1, W2, (__half*)p_sup2h, N);

    gather2_kernel<<<(N * 32 + 255) / 256, 256>>>(
        (const int*)p_off, (const int2*)p_csr, (const __half*)p_sup2h,
        b2, out, N);
}

// round 16
// speedup vs baseline: 1.1779x; 1.0873x over previous
#include <cuda_runtime.h>
#include <cuda_fp16.h>
#include <cuda_bf16.h>
#include <mma.h>
#include <math.h>

using namespace nvcuda;

// Problem constants (fixed by the dataset)
#define NNODES 100000
#define MAXE   1600000
#define NFEAT  128
#define NHID   64
#define NCLASS 16

// Scratch buffers.
__device__ __align__(128) uint4  g_sup1h[NNODES * 8];   // N x 64 fp16 (x @ W1)
__device__ __align__(128) __half g_sup2h[NNODES * 16];  // N x 16 fp16 (h @ W2)
__device__ __align__(128) int g_work[NNODES + 128];     // [0,N): cnt/cursor, [N,N+128): scan aggs
__device__ int  g_off[NNODES + 1];   // CSR offsets
__device__ int2 g_csr[MAXE];         // packed {src, float_as_int(w)}

// ---------------------------------------------------------------------------
// GEMM1 (HMMA): sup1[N,64] = x[N,128] @ W1[128,64], fp16 in, fp32 acc,
// fp16 out. 128x64 block tile, KC=64 (2 phases), 8 warps, warp = 16 rows.
// ---------------------------------------------------------------------------
__global__ void __launch_bounds__(256) gemm1_kernel(
        const float* __restrict__ x,
        const float* __restrict__ W1,
        uint4* __restrict__ outh, int N) {
    __shared__ __align__(16) char smem[32768];
    __half (*sA)[72] = (__half(*)[72])smem;                  // 128 x 72 halves
    __half (*sB)[72] = (__half(*)[72])(smem + 128 * 72 * 2); // 64 x 72 halves
    float (*sO)[64]  = (float(*)[64])smem;                   // epilogue alias

    int tid = threadIdx.x;
    int w = tid >> 5;
    int lane = tid & 31;
    int rb = blockIdx.x * 128;

    wmma::fragment<wmma::accumulator, 16, 16, 16, float> acc[4];
#pragma unroll
    for (int i = 0; i < 4; i++) wmma::fill_fragment(acc[i], 0.f);

#pragma unroll
    for (int kb = 0; kb < NFEAT; kb += 64) {
#pragma unroll
        for (int it = 0; it < 8; it++) {
            int idx = tid + it * 256;
            int row = idx >> 4;
            int cc = (idx & 15) * 4;
            float4 v = make_float4(0.f, 0.f, 0.f, 0.f);
            if (rb + row < N)
                v = *(const float4*)&x[(size_t)(rb + row) * NFEAT + kb + cc];
            *(__half2*)&sA[row][cc]     = __floats2half2_rn(v.x, v.y);
            *(__half2*)&sA[row][cc + 2] = __floats2half2_rn(v.z, v.w);
        }
#pragma unroll
        for (int it = 0; it < 4; it++) {
            int idx = tid + it * 256;
            int row = idx >> 4;
            int cc = (idx & 15) * 4;
            float4 v = *(const float4*)&W1[(size_t)(kb + row) * NHID + cc];
            *(__half2*)&sB[row][cc]     = __floats2half2_rn(v.x, v.y);
            *(__half2*)&sB[row][cc + 2] = __floats2half2_rn(v.z, v.w);
        }
        __syncthreads();

#pragma unroll
        for (int ks = 0; ks < 64; ks += 16) {
            wmma::fragment<wmma::matrix_a, 16, 16, 16, __half, wmma::row_major> fa;
            wmma::load_matrix_sync(fa, &sA[w * 16][ks], 72);
#pragma unroll
            for (int nt = 0; nt < 4; nt++) {
                wmma::fragment<wmma::matrix_b, 16, 16, 16, __half, wmma::row_major> fb;
                wmma::load_matrix_sync(fb, &sB[ks][nt * 16], 72);
                wmma::mma_sync(acc[nt], fa, fb, acc[nt]);
            }
        }
        __syncthreads();
    }

#pragma unroll
    for (int nt = 0; nt < 4; nt++)
        wmma::store_matrix_sync(&sO[w * 16][nt * 16], acc[nt], 64, wmma::mem_row_major);
    __syncwarp();

#pragma unroll
    for (int q = 0; q < 4; q++) {
        int idx = lane + q * 32;
        int r = idx >> 3;
        int c8 = idx & 7;
        int row = rb + w * 16 + r;
        if (row < N) {
            const float* p = &sO[w * 16 + r][c8 * 8];
            __half2 h0 = __floats2half2_rn(p[0], p[1]);
            __half2 h1 = __floats2half2_rn(p[2], p[3]);
            __half2 h2 = __floats2half2_rn(p[4], p[5]);
            __half2 h3 = __floats2half2_rn(p[6], p[7]);
            uint4 o;
            o.x = *(unsigned*)&h0; o.y = *(unsigned*)&h1;
            o.z = *(unsigned*)&h2; o.w = *(unsigned*)&h3;
            outh[(size_t)row * 8 + c8] = o;
        }
    }
}

// ---------------------------------------------------------------------------
// CSR build
// ---------------------------------------------------------------------------
// Histogram: 4 consecutive edges per thread via one LDG.128.
__global__ void __launch_bounds__(256) hist_kernel(
        const int* __restrict__ dst, int* __restrict__ cnt, int E) {
    int e4 = (blockIdx.x * blockDim.x + threadIdx.x) * 4;
    if (e4 + 3 < E) {
        int4 d = *(const int4*)&dst[e4];
        atomicAdd(&cnt[d.x], 1);
        atomicAdd(&cnt[d.y], 1);
        atomicAdd(&cnt[d.z], 1);
        atomicAdd(&cnt[d.w], 1);
    } else {
        for (int e = e4; e < E; e++) atomicAdd(&cnt[dst[e]], 1);
    }
}

// Fused exclusive scan with decoupled lookback (98 blocks). Also initializes
// the permute cursor. Deadlock-free: blocks only wait on lower block ids.
__global__ void __launch_bounds__(1024) scan_fused(
        const int* __restrict__ cnt,
        int* __restrict__ off,
        int* __restrict__ cursor,
        volatile int* __restrict__ aggp,   // zeroed before launch; agg+1
        int n, int E) {
    __shared__ int s[1024];
    __shared__ int s_prefix;
    int b = blockIdx.x;
    int i = b * 1024 + threadIdx.x;
    int v = (i < n) ? cnt[i] : 0;
    s[threadIdx.x] = v;
    __syncthreads();
#pragma unroll
    for (int d = 1; d < 1024; d <<= 1) {
        int t = (threadIdx.x >= d) ? s[threadIdx.x - d] : 0;
        __syncthreads();
        s[threadIdx.x] += t;
        __syncthreads();
    }
    int local_excl = s[threadIdx.x] - v;
    int total = s[1023];

    if (threadIdx.x == 0) {
        __threadfence();
        aggp[b] = total + 1;
    }

    int contrib = 0;
    if (threadIdx.x < (unsigned)b) {
        int a;
        do { a = aggp[threadIdx.x]; } while (a == 0);
        contrib = a - 1;
    }
    __syncthreads();
    s[threadIdx.x] = contrib;
    __syncthreads();
#pragma unroll
    for (int d = 512; d; d >>= 1) {
        if (threadIdx.x < d) s[threadIdx.x] += s[threadIdx.x + d];
        __syncthreads();
    }
    if (threadIdx.x == 0) s_prefix = s[0];
    __syncthreads();
    int prefix = s_prefix;

    if (i < n) {
        int o = local_excl + prefix;
        off[i] = o;
        cursor[i] = o;
    }
    if (i == 0) off[n] = E;
}

// Permute: 4 consecutive edges per thread via 3x LDG.128.
__global__ void __launch_bounds__(256) permute_kernel(
        const int* __restrict__ src,
        const int* __restrict__ dst,
        const float* __restrict__ ew,
        int* __restrict__ cursor,
        int2* __restrict__ csr, int E) {
    int e4 = (blockIdx.x * blockDim.x + threadIdx.x) * 4;
    if (e4 + 3 < E) {
        int4 d = *(const int4*)&dst[e4];
        int4 s = *(const int4*)&src[e4];
        float4 w = *(const float4*)&ew[e4];
        int p0 = atomicAdd(&cursor[d.x], 1);
        int p1 = atomicAdd(&cursor[d.y], 1);
        int p2 = atomicAdd(&cursor[d.z], 1);
        int p3 = atomicAdd(&cursor[d.w], 1);
        csr[p0] = make_int2(s.x, __float_as_int(w.x));
        csr[p1] = make_int2(s.y, __float_as_int(w.y));
        csr[p2] = make_int2(s.z, __float_as_int(w.z));
        csr[p3] = make_int2(s.w, __float_as_int(w.w));
    } else {
        for (int e = e4; e < E; e++) {
            int p = atomicAdd(&cursor[dst[e]], 1);
            csr[p] = make_int2(src[e], __float_as_int(ew[e]));
        }
    }
}

// ---------------------------------------------------------------------------
// Gather stage 1 (fused): half-warp per edge — 16 lanes x uint2 (8B) cover
// one 128B fp16 row; warp processes 2 edges concurrently, x4 unroll -> 8
// gathers in flight. Then h = relu(agg+b1), sup2 = fp16(h @ W2) via smem.
// ---------------------------------------------------------------------------
__global__ void __launch_bounds__(256) gather1_kernel(
        const int* __restrict__ off,
        const int2* __restrict__ csr,
        const unsigned* __restrict__ suph,   // N x 32 half2 words
        const float* __restrict__ b1,
        const float* __restrict__ W2,
        __half* __restrict__ sup2h, int N) {
    __shared__ float sW[NHID * NCLASS];  // 4 KB
    __shared__ float sb[NHID];
    __shared__ __align__(16) float sh[8][NHID];  // per-warp h row
    for (int i = threadIdx.x; i < NHID * NCLASS; i += blockDim.x) sW[i] = W2[i];
    if (threadIdx.x < NHID) sb[threadIdx.x] = b1[threadIdx.x];
    __syncthreads();

    int warp = (blockIdx.x * blockDim.x + threadIdx.x) >> 5;
    int wid = (threadIdx.x >> 5);
    int lane = threadIdx.x & 31;
    if (warp >= N) return;
    int g16 = lane >> 4;     // edge slot (0/1)
    int l16 = lane & 15;     // covers hid values 4*l16 .. 4*l16+3

    int beg = off[warp], end = off[warp + 1];
    float a0 = 0.f, a1 = 0.f, a2 = 0.f, a3 = 0.f;
    int j = beg + g16;
    for (; j + 6 < end; j += 8) {     // 4 edges for this half-warp
        int2 e0 = csr[j], e1 = csr[j + 2], e2 = csr[j + 4], e3 = csr[j + 6];
        uint2 u0 = *(const uint2*)&suph[(size_t)e0.x * 32 + l16 * 2];
        uint2 u1 = *(const uint2*)&suph[(size_t)e1.x * 32 + l16 * 2];
        uint2 u2 = *(const uint2*)&suph[(size_t)e2.x * 32 + l16 * 2];
        uint2 u3 = *(const uint2*)&suph[(size_t)e3.x * 32 + l16 * 2];
        float w0 = __int_as_float(e0.y), w1 = __int_as_float(e1.y);
        float w2 = __int_as_float(e2.y), w3 = __int_as_float(e3.y);
        float2 f;
        f = __half22float2(*(__half2*)&u0.x); a0 += w0 * f.x; a1 += w0 * f.y;
        f = __half22float2(*(__half2*)&u0.y); a2 += w0 * f.x; a3 += w0 * f.y;
        f = __half22float2(*(__half2*)&u1.x); a0 += w1 * f.x; a1 += w1 * f.y;
        f = __half22float2(*(__half2*)&u1.y); a2 += w1 * f.x; a3 += w1 * f.y;
        f = __half22float2(*(__half2*)&u2.x); a0 += w2 * f.x; a1 += w2 * f.y;
        f = __half22float2(*(__half2*)&u2.y); a2 += w2 * f.x; a3 += w2 * f.y;
        f = __half22float2(*(__half2*)&u3.x); a0 += w3 * f.x; a1 += w3 * f.y;
        f = __half22float2(*(__half2*)&u3.y); a2 += w3 * f.x; a3 += w3 * f.y;
    }
    for (; j < end; j += 2) {
        int2 ed = csr[j];
        float w = __int_as_float(ed.y);
        uint2 u = *(const uint2*)&suph[(size_t)ed.x * 32 + l16 * 2];
        float2 f;
        f = __half22float2(*(__half2*)&u.x); a0 += w * f.x; a1 += w * f.y;
        f = __half22float2(*(__half2*)&u.y); a2 += w * f.x; a3 += w * f.y;
    }
    // Combine the two edge-slot halves.
    a0 += __shfl_down_sync(0xffffffffu, a0, 16);
    a1 += __shfl_down_sync(0xffffffffu, a1, 16);
    a2 += __shfl_down_sync(0xffffffffu, a2, 16);
    a3 += __shfl_down_sync(0xffffffffu, a3, 16);
    if (lane < 16) {
        float4 hv = make_float4(fmaxf(a0 + sb[4 * l16 + 0], 0.f),
                                fmaxf(a1 + sb[4 * l16 + 1], 0.f),
                                fmaxf(a2 + sb[4 * l16 + 2], 0.f),
                                fmaxf(a3 + sb[4 * l16 + 3], 0.f));
        *(float4*)&sh[wid][4 * l16] = hv;
    }
    __syncwarp();

    // Projection: lanes 0-15 take even k, 16-31 odd k; c = lane & 15.
    int c = lane & 15;
    int kh = lane >> 4;
    float acc = 0.f;
#pragma unroll
    for (int i = 0; i < 32; i++) {
        int k = 2 * i + kh;
        acc += sh[wid][k] * sW[k * NCLASS + c];
    }
    acc += __shfl_down_sync(0xffffffffu, acc, 16);
    if (lane < 16) sup2h[(size_t)warp * NCLASS + lane] = __float2half_rn(acc);
}

// ---------------------------------------------------------------------------
// Gather stage 2 (fused): 8 lanes per edge, half2 loads (lane owns 2
// classes); 4 edges/warp concurrently, x2 unroll -> 8 in flight. Then
// +b2 and 16-wide log_softmax in 8 lanes (float2 per lane).
// ---------------------------------------------------------------------------
__global__ void __launch_bounds__(256) gather2_kernel(
        const int* __restrict__ off,
        const int2* __restrict__ csr,
        const __half* __restrict__ sup2h,
        const float* __restrict__ b2,
        float* __restrict__ out, int N) {
    int warp = (blockIdx.x * blockDim.x + threadIdx.x) >> 5;
    int lane = threadIdx.x & 31;
    if (warp >= N) return;
    int g8 = lane >> 3;     // edge slot (0..3)
    int l8 = lane & 7;      // class pair (2*l8, 2*l8+1)

    int beg = off[warp], end = off[warp + 1];
    float ax = 0.f, ay = 0.f;
    int j = beg + g8;
    for (; j + 4 < end; j += 8) {     // 2 edges for this 8-lane group
        int2 ea = csr[j];
        int2 eb = csr[j + 4];
        unsigned ua = *(const unsigned*)&sup2h[(size_t)ea.x * NCLASS + l8 * 2];
        unsigned ub = *(const unsigned*)&sup2h[(size_t)eb.x * NCLASS + l8 * 2];
        float wa = __int_as_float(ea.y), wb = __int_as_float(eb.y);
        float2 fa = __half22float2(*(__half2*)&ua);
        float2 fb = __half22float2(*(__half2*)&ub);
        ax += wa * fa.x + wb * fb.x;
        ay += wa * fa.y + wb * fb.y;
    }
    for (; j < end; j += 4) {
        int2 ed = csr[j];
        unsigned u = *(const unsigned*)&sup2h[(size_t)ed.x * NCLASS + l8 * 2];
        float w = __int_as_float(ed.y);
        float2 f = __half22float2(*(__half2*)&u);
        ax += w * f.x;
        ay += w * f.y;
    }
    // Combine the 4 edge-slot groups (lanes 0-7 end with totals).
    ax += __shfl_down_sync(0xffffffffu, ax, 16);
    ay += __shfl_down_sync(0xffffffffu, ay, 16);
    ax += __shfl_down_sync(0xffffffffu, ax, 8);
    ay += __shfl_down_sync(0xffffffffu, ay, 8);

    float2 bb = *(const float2*)&b2[l8 * 2];
    float v0 = ax + bb.x;
    float v1 = ay + bb.y;
    // 16-wide log_softmax across 8 lanes x 2 values (xor stays within 0-7).
    float m = fmaxf(v0, v1);
#pragma unroll
    for (int d = 4; d; d >>= 1) m = fmaxf(m, __shfl_xor_sync(0xffffffffu, m, d));
    float ex = expf(v0 - m) + expf(v1 - m);
#pragma unroll
    for (int d = 4; d; d >>= 1) ex += __shfl_xor_sync(0xffffffffu, ex, d);
    float lse = m + logf(ex);
    if (lane < 8)
        *(float2*)&out[(size_t)warp * NCLASS + l8 * 2] = make_float2(v0 - lse, v1 - lse);
}

extern "C" void kernel_launch(void* const* d_in, const int* in_sizes, int n_in,
                              void* d_out, int out_size) {
    const float* x  = (const float*)d_in[0];
    const int*   src = (const int*)d_in[1];
    const int*   dst = (const int*)d_in[2];
    const float* ew  = (const float*)d_in[3];
    const float* W1  = (const float*)d_in[4];
    const float* b1  = (const float*)d_in[5];
    const float* W2  = (const float*)d_in[6];
    const float* b2  = (const float*)d_in[7];
    float* out = (float*)d_out;

    int N = in_sizes[0] / NFEAT;   // 100000
    int E = in_sizes[1];           // 1600000

    void *p_sup1h, *p_sup2h, *p_work, *p_off, *p_csr;
    cudaGetSymbolAddress(&p_sup1h, g_sup1h);
    cudaGetSymbolAddress(&p_sup2h, g_sup2h);
    cudaGetSymbolAddress(&p_work, g_work);
    cudaGetSymbolAddress(&p_off, g_off);
    cudaGetSymbolAddress(&p_csr, g_csr);

    int* p_cnt = (int*)p_work;             // [0, N)
    int* p_agg = ((int*)p_work) + N;       // [N, N+128)

    int nb_scan = (N + 1023) / 1024;   // 98

    // Fork: gemm1 on a side stream, overlapped with the CSR build.
    cudaStream_t s1;
    cudaStreamCreateWithFlags(&s1, cudaStreamNonBlocking);
    cudaEvent_t e0, e1;
    cudaEventCreateWithFlags(&e0, cudaEventDisableTiming);
    cudaEventCreateWithFlags(&e1, cudaEventDisableTiming);

    cudaEventRecord(e0, 0);
    cudaStreamWaitEvent(s1, e0, 0);
    gemm1_kernel<<<(N + 127) / 128, 256, 0, s1>>>(x, W1, (uint4*)p_sup1h, N);
    cudaEventRecord(e1, s1);

    // --- CSR build (main stream) ---
    cudaMemsetAsync(p_work, 0, (size_t)(N + 128) * sizeof(int));  // cnt + aggs
    {
        int q = (E + 3) / 4;
        hist_kernel<<<(q + 255) / 256, 256>>>(dst, p_cnt, E);
    }
    scan_fused<<<nb_scan, 1024>>>((const int*)p_cnt, (int*)p_off, p_cnt,
                                  (volatile int*)p_agg, N, E);
    {
        int q = (E + 3) / 4;
        permute_kernel<<<(q + 255) / 256, 256>>>(src, dst, ew, p_cnt,
                                                 (int2*)p_csr, E);
    }

    // Join: gathers need both CSR and sup1.
    cudaStreamWaitEvent(0, e1, 0);

    gather1_kernel<<<(N * 32 + 255) / 256, 256>>>(
        (const int*)p_off, (const int2*)p_csr, (const unsigned*)p_sup1h,
        b1, W2, (__half*)p_sup2h, N);

    gather2_kernel<<<(N * 32 + 255) / 256, 256>>>(
        (const int*)p_off, (const int2*)p_csr, (const __half*)p_sup2h,
        b2, out, N);
}